// round 4
// baseline (speedup 1.0000x reference)
#include <cuda_runtime.h>
#include <math.h>

#define T_STEPS 1024
#define NB 128
#define FD 128
#define HD 128

// Scratch: 8 precomputed floats per (b,t):
//  [0:4) = x_t @ W_in_x^T + b_in   (x-part of y)
//  [4:8) = vqc(x_t @ W_x^T + b_x, vqc_w[2])  (fully h-independent)
__device__ float g_xpre[NB * T_STEPS * 8];

typedef unsigned long long u64;

__device__ __forceinline__ u64 pack2(float lo, float hi) {
    u64 r;
    asm("mov.b64 %0, {%1, %2};" : "=l"(r) : "f"(lo), "f"(hi));
    return r;
}
__device__ __forceinline__ void unpack2(u64 v, float& lo, float& hi) {
    asm("mov.b64 {%0, %1}, %2;" : "=f"(lo), "=f"(hi) : "l"(v));
}
// Blackwell packed fp32 pair ops
__device__ __forceinline__ u64 fma2(u64 a, u64 b, u64 c) {
    u64 r;
    asm("fma.rn.f32x2 %0, %1, %2, %3;" : "=l"(r) : "l"(a), "l"(b), "l"(c));
    return r;
}
__device__ __forceinline__ u64 add2(u64 a, u64 b) {
    u64 r;
    asm("add.rn.f32x2 %0, %1, %2;" : "=l"(r) : "l"(a), "l"(b));
    return r;
}

__device__ __forceinline__ float fsig(float x) {
    return __fdividef(1.0f, 1.0f + __expf(-x));
}
__device__ __forceinline__ float ftanhf(float x) {
    float e = __expf(-2.0f * x);
    return __fdividef(1.0f - e, 1.0f + e);
}

// ---------------------------------------------------------------------------
// Pre-pass: one warp per (b,t) row, grid-stride. Memory bound (~64MB read).
// ---------------------------------------------------------------------------
__global__ void __launch_bounds__(256) qgru_prepass(
    const float* __restrict__ x,
    const float* __restrict__ W_in, const float* __restrict__ b_in,
    const float* __restrict__ W_x,  const float* __restrict__ b_x,
    const float* __restrict__ vqc_w)
{
    const int lane = threadIdx.x & 31;
    const int gw   = (blockIdx.x * blockDim.x + threadIdx.x) >> 5;
    const int nw   = (gridDim.x * blockDim.x) >> 5;

    float wt[8][4];
#pragma unroll
    for (int k = 0; k < 4; k++) {
#pragma unroll
        for (int i = 0; i < 4; i++) {
            wt[k][i]     = W_in[k * (HD + FD) + HD + lane * 4 + i];
            wt[4 + k][i] = W_x[k * FD + lane * 4 + i];
        }
    }
    float bi[8], w2[4];
#pragma unroll
    for (int k = 0; k < 4; k++) {
        bi[k]     = b_in[k];
        bi[4 + k] = b_x[k];
        w2[k]     = vqc_w[2 * 4 + k];
    }

    const int NROWS = NB * T_STEPS;
    for (int row = gw; row < NROWS; row += nw) {
        float4 xv = *reinterpret_cast<const float4*>(x + (size_t)row * FD + lane * 4);
        float s[8];
#pragma unroll
        for (int k = 0; k < 8; k++) {
            s[k] = wt[k][0] * xv.x;
            s[k] = fmaf(wt[k][1], xv.y, s[k]);
            s[k] = fmaf(wt[k][2], xv.z, s[k]);
            s[k] = fmaf(wt[k][3], xv.w, s[k]);
        }
#pragma unroll
        for (int off = 16; off; off >>= 1) {
#pragma unroll
            for (int k = 0; k < 8; k++)
                s[k] += __shfl_xor_sync(0xffffffffu, s[k], off);
        }
        if (lane == 0) {
            float c0 = __cosf(s[4] + bi[4] + w2[0]);
            float c1 = __cosf(s[5] + bi[5] + w2[1]);
            float c2 = __cosf(s[6] + bi[6] + w2[2]);
            float c3 = __cosf(s[7] + bi[7] + w2[3]);
            float z1 = c0 * c1;
            float z2 = z1 * c2;
            float4 o0 = make_float4(s[0] + bi[0], s[1] + bi[1],
                                    s[2] + bi[2], s[3] + bi[3]);
            float4 o1 = make_float4(c1 * c2 * c3, z1, z2, z2 * c3);
            float4* op = reinterpret_cast<float4*>(g_xpre + (size_t)row * 8);
            op[0] = o0;
            op[1] = o1;
        }
    }
}

// ---------------------------------------------------------------------------
// Sequential recurrence: 1 CTA per batch row, 128 threads (thread j owns
// output column j). Dot products: lane = 4*k + part owns sum k over
// h[32*part .. 32*part+32). 2-shuffle butterfly within each lane quad.
// Cosines distributed via per-warp smem slot (STS + syncwarp + 3 LDS.128)
// instead of 12 shuffles. xpre for the whole row staged in smem.
// ---------------------------------------------------------------------------
__global__ void __launch_bounds__(128, 1) qgru_seq(
    const float* __restrict__ W_in, const float* __restrict__ W_h,
    const float* __restrict__ b_h,
    const float* __restrict__ W_out, const float* __restrict__ b_out,
    const float* __restrict__ vqc_w,
    float* __restrict__ out)
{
    const int b    = blockIdx.x;
    const int j    = threadIdx.x;
    const int lane = j & 31;
    const int wid  = j >> 5;
    const int k    = lane >> 2;   // sum index 0..7
    const int part = lane & 3;    // h slice [32*part, 32*part+32)

    __shared__ __align__(16) float xs[T_STEPS * 8];     // 32 KB staged xpre row
    __shared__ __align__(16) float h_sh[2][HD];
    __shared__ __align__(16) float cos_sh[4][16];       // 12 used per warp

    // ---- stage this row's xpre into smem (16 LDG.128 in flight per thread)
    {
        const float4* src = reinterpret_cast<const float4*>(
            g_xpre + (size_t)b * T_STEPS * 8);
        float4* dst = reinterpret_cast<float4*>(xs);
        float4 tmp[16];
#pragma unroll
        for (int i = 0; i < 16; i++) tmp[i] = src[j + 128 * i];
#pragma unroll
        for (int i = 0; i < 16; i++) dst[j + 128 * i] = tmp[i];
    }

    // ---- weights for this lane's sum k over its 32 h elements (packed pairs)
    // k<4 -> W_in[k, 0:128] (h-part of y); k>=4 -> W_h[k-4, :]
    const float* wrow = (k < 4) ? (W_in + k * (HD + FD)) : (W_h + (k - 4) * HD);
    u64 wp[16];
#pragma unroll
    for (int i = 0; i < 8; i++) {
        float4 wv = *reinterpret_cast<const float4*>(wrow + part * 32 + 4 * i);
        wp[2 * i]     = pack2(wv.x, wv.y);
        wp[2 * i + 1] = pack2(wv.z, wv.w);
    }

    float wo[4];
#pragma unroll
    for (int kk = 0; kk < 4; kk++) wo[kk] = W_out[j * 4 + kk];
    const float bo = b_out[j];

    // ---- cosine role for this lane (loop-invariant)
    // sum k<4 (y): part==0 -> cr_k (slot k, +vqc_w[0][k]); part==1 -> cz_k (slot 4+k, +vqc_w[1][k])
    // sum k>=4 (q): part==0 -> ch_{k-4} (slot 8+k-4, +vqc_w[3][k-4]+b_h[k-4])
    const bool is_r = (part == 0) && (k < 4);
    const bool is_z = (part == 1) && (k < 4);
    const bool is_h = (part == 0) && (k >= 4);
    const int  slot = is_r ? k : (is_z ? 4 + k : (is_h ? 8 + (k - 4) : -1));
    float cadd = 0.0f;
    if (is_r) cadd = vqc_w[k];
    if (is_z) cadd = vqc_w[4 + k];
    if (is_h) cadd = vqc_w[12 + (k - 4)] + b_h[k - 4];
    const bool use_p = (k < 4);
    const int  pidx  = k & 3;      // xs component for y lanes

    float hj = 0.0f;
    h_sh[0][j] = 0.0f;

    // c_last = zeros
    out[(size_t)NB * T_STEPS * HD + (size_t)NB * HD + b * HD + j] = 0.0f;

    float* __restrict__ orow = out + (size_t)b * T_STEPS * HD + j;
    float* cbuf = cos_sh[wid];

    __syncthreads();

#pragma unroll 1
    for (int t = 0; t < T_STEPS; t++) {
        const ulonglong2* hp = reinterpret_cast<const ulonglong2*>(
            h_sh[t & 1] + part * 32);

        u64 a0 = 0ull, a1 = 0ull, a2 = 0ull, a3 = 0ull;
#pragma unroll
        for (int i = 0; i < 2; i++) {
            ulonglong2 h0 = hp[4 * i + 0];
            ulonglong2 h1 = hp[4 * i + 1];
            ulonglong2 h2 = hp[4 * i + 2];
            ulonglong2 h3 = hp[4 * i + 3];
            a0 = fma2(h0.x, wp[8 * i + 0], a0);
            a1 = fma2(h0.y, wp[8 * i + 1], a1);
            a2 = fma2(h1.x, wp[8 * i + 2], a2);
            a3 = fma2(h1.y, wp[8 * i + 3], a3);
            a0 = fma2(h2.x, wp[8 * i + 4], a0);
            a1 = fma2(h2.y, wp[8 * i + 5], a1);
            a2 = fma2(h3.x, wp[8 * i + 6], a2);
            a3 = fma2(h3.y, wp[8 * i + 7], a3);
        }
        a0 = add2(a0, a1);
        a2 = add2(a2, a3);
        a0 = add2(a0, a2);
        float lo, hi;
        unpack2(a0, lo, hi);
        float s = lo + hi;

        // 2-level butterfly within the lane quad owning sum k
        s += __shfl_xor_sync(0xffffffffu, s, 1);
        s += __shfl_xor_sync(0xffffffffu, s, 2);

        // one warp-wide cosine computes this warp's 12 gate cosines
        float pc  = xs[t * 8 + pidx];
        float arg = s + cadd + (use_p ? pc : 0.0f);
        float cv  = __cosf(arg);
        if (slot >= 0) cbuf[slot] = cv;
        __syncwarp();

        float4 CR = *reinterpret_cast<const float4*>(cbuf + 0);
        float4 CZ = *reinterpret_cast<const float4*>(cbuf + 4);
        float4 CH = *reinterpret_cast<const float4*>(cbuf + 8);
        float4 P1 = *reinterpret_cast<const float4*>(xs + t * 8 + 4);

        // z-expectations after CNOT ring: (C1C2C3, C0C1, C0C1C2, C0C1C2C3)
        float rm = CR.y * CR.z;
        float rA = CR.x * CR.y, rB = CR.x * rm;
        float o_r = fmaf(rm * CR.w, wo[0],
                    fmaf(rA, wo[1], fmaf(rB, wo[2], fmaf(rB * CR.w, wo[3], bo))));
        float Er = __expf(-o_r);                 // start r's MUFU chain early

        float hm = CH.y * CH.z;
        float hA = CH.x * CH.y, hB = CH.x * hm;
        float o_h = fmaf(hm * CH.w, wo[0],
                    fmaf(hA, wo[1], fmaf(hB, wo[2], fmaf(hB * CH.w, wo[3], bo))));

        float zm = CZ.y * CZ.z;
        float zA = CZ.x * CZ.y, zB = CZ.x * zm;
        float o_z = fmaf(zm * CZ.w, wo[0],
                    fmaf(zA, wo[1], fmaf(zB, wo[2], fmaf(zB * CZ.w, wo[3], bo))));

        float o_x = fmaf(P1.x, wo[0],
                    fmaf(P1.y, wo[1], fmaf(P1.z, wo[2], fmaf(P1.w, wo[3], bo))));

        float r = __fdividef(1.0f, 1.0f + Er);
        float z = fsig(o_z);
        float n = ftanhf(fmaf(r, o_h, o_x));

        hj = fmaf(z, hj - n, n);          // (1-z)*n + z*h

        h_sh[(t + 1) & 1][j] = hj;        // publish to other lanes
        orow[(size_t)t * HD] = hj;        // hidden_seq[b, t, j]

        __syncthreads();
    }

    // h_last
    out[(size_t)NB * T_STEPS * HD + b * HD + j] = hj;
}

extern "C" void kernel_launch(void* const* d_in, const int* in_sizes, int n_in,
                              void* d_out, int out_size) {
    const float* x     = (const float*)d_in[0];
    const float* W_in  = (const float*)d_in[1];
    const float* b_in  = (const float*)d_in[2];
    const float* W_x   = (const float*)d_in[3];
    const float* b_x   = (const float*)d_in[4];
    const float* W_h   = (const float*)d_in[5];
    const float* b_h   = (const float*)d_in[6];
    const float* W_out = (const float*)d_in[7];
    const float* b_out = (const float*)d_in[8];
    const float* vqcw  = (const float*)d_in[9];
    float* out = (float*)d_out;

    qgru_prepass<<<592, 256>>>(x, W_in, b_in, W_x, b_x, vqcw);
    qgru_seq<<<NB, HD>>>(W_in, W_h, b_h, W_out, b_out, vqcw, out);
}

// round 5
// speedup vs baseline: 1.2919x; 1.2919x over previous
#include <cuda_runtime.h>
#include <math.h>

#define T_STEPS 1024
#define NB 128
#define FD 128
#define HD 128

// Scratch: 8 precomputed floats per (b,t):
//  [0:4) = x_t @ W_in_x^T + b_in   (x-part of y)
//  [4:8) = vqc(x_t @ W_x^T + b_x, vqc_w[2])  (fully h-independent)
__device__ float g_xpre[NB * T_STEPS * 8];

typedef unsigned long long u64;

__device__ __forceinline__ u64 pack2(float lo, float hi) {
    u64 r;
    asm("mov.b64 %0, {%1, %2};" : "=l"(r) : "f"(lo), "f"(hi));
    return r;
}
__device__ __forceinline__ void unpack2(u64 v, float& lo, float& hi) {
    asm("mov.b64 {%0, %1}, %2;" : "=f"(lo), "=f"(hi) : "l"(v));
}
// Blackwell packed fp32 pair ops
__device__ __forceinline__ u64 fma2(u64 a, u64 b, u64 c) {
    u64 r;
    asm("fma.rn.f32x2 %0, %1, %2, %3;" : "=l"(r) : "l"(a), "l"(b), "l"(c));
    return r;
}
__device__ __forceinline__ u64 add2(u64 a, u64 b) {
    u64 r;
    asm("add.rn.f32x2 %0, %1, %2;" : "=l"(r) : "l"(a), "l"(b));
    return r;
}

__device__ __forceinline__ float fsig(float x) {
    return __fdividef(1.0f, 1.0f + __expf(-x));
}
__device__ __forceinline__ float ftanhf(float x) {
    float e = __expf(-2.0f * x);
    return __fdividef(1.0f - e, 1.0f + e);
}

// ---------------------------------------------------------------------------
// Pre-pass: one warp per (b,t) row, grid-stride. Memory bound (~64MB read).
// ---------------------------------------------------------------------------
__global__ void __launch_bounds__(256) qgru_prepass(
    const float* __restrict__ x,
    const float* __restrict__ W_in, const float* __restrict__ b_in,
    const float* __restrict__ W_x,  const float* __restrict__ b_x,
    const float* __restrict__ vqc_w)
{
    const int lane = threadIdx.x & 31;
    const int gw   = (blockIdx.x * blockDim.x + threadIdx.x) >> 5;
    const int nw   = (gridDim.x * blockDim.x) >> 5;

    float wt[8][4];
#pragma unroll
    for (int k = 0; k < 4; k++) {
#pragma unroll
        for (int i = 0; i < 4; i++) {
            wt[k][i]     = W_in[k * (HD + FD) + HD + lane * 4 + i];
            wt[4 + k][i] = W_x[k * FD + lane * 4 + i];
        }
    }
    float bi[8], w2[4];
#pragma unroll
    for (int k = 0; k < 4; k++) {
        bi[k]     = b_in[k];
        bi[4 + k] = b_x[k];
        w2[k]     = vqc_w[2 * 4 + k];
    }

    const int NROWS = NB * T_STEPS;
    for (int row = gw; row < NROWS; row += nw) {
        float4 xv = *reinterpret_cast<const float4*>(x + (size_t)row * FD + lane * 4);
        float s[8];
#pragma unroll
        for (int k = 0; k < 8; k++) {
            s[k] = wt[k][0] * xv.x;
            s[k] = fmaf(wt[k][1], xv.y, s[k]);
            s[k] = fmaf(wt[k][2], xv.z, s[k]);
            s[k] = fmaf(wt[k][3], xv.w, s[k]);
        }
#pragma unroll
        for (int off = 16; off; off >>= 1) {
#pragma unroll
            for (int k = 0; k < 8; k++)
                s[k] += __shfl_xor_sync(0xffffffffu, s[k], off);
        }
        if (lane == 0) {
            float c0 = __cosf(s[4] + bi[4] + w2[0]);
            float c1 = __cosf(s[5] + bi[5] + w2[1]);
            float c2 = __cosf(s[6] + bi[6] + w2[2]);
            float c3 = __cosf(s[7] + bi[7] + w2[3]);
            float z1 = c0 * c1;
            float z2 = z1 * c2;
            float4 o0 = make_float4(s[0] + bi[0], s[1] + bi[1],
                                    s[2] + bi[2], s[3] + bi[3]);
            float4 o1 = make_float4(c1 * c2 * c3, z1, z2, z2 * c3);
            float4* op = reinterpret_cast<float4*>(g_xpre + (size_t)row * 8);
            op[0] = o0;
            op[1] = o1;
        }
    }
}

// ---------------------------------------------------------------------------
// Sequential recurrence: 1 CTA per batch row, 128 threads (thread j owns
// output column j). Dot layout: lane = 8m+sub; m owns sums {2m, 2m+1} over
// h[16*sub .. 16*sub+16) -> 4 LDS.128/lane (64 crossbar wavefronts per CTA
// step, half of the previous layout), 3-level butterfly.
// Cosines distributed via per-warp smem slot. xpre row staged in smem.
// o_x computed off the critical path; hidden-seq STG moved past the barrier.
// ---------------------------------------------------------------------------
__global__ void __launch_bounds__(128, 1) qgru_seq(
    const float* __restrict__ W_in, const float* __restrict__ W_h,
    const float* __restrict__ b_h,
    const float* __restrict__ W_out, const float* __restrict__ b_out,
    const float* __restrict__ vqc_w,
    float* __restrict__ out)
{
    const int b    = blockIdx.x;
    const int j    = threadIdx.x;
    const int lane = j & 31;
    const int wid  = j >> 5;
    const int m    = lane >> 3;   // sum pair {2m, 2m+1}
    const int sub  = lane & 7;    // h slice [16*sub, 16*sub+16)

    __shared__ __align__(16) float xs[T_STEPS * 8];     // 32 KB staged xpre row
    __shared__ __align__(16) float h_sh[2][HD];
    __shared__ __align__(16) float cos_sh[4][16];       // 12 used per warp

    // ---- stage this row's xpre into smem
    {
        const float4* src = reinterpret_cast<const float4*>(
            g_xpre + (size_t)b * T_STEPS * 8);
        float4* dst = reinterpret_cast<float4*>(xs);
        float4 tmp[16];
#pragma unroll
        for (int i = 0; i < 16; i++) tmp[i] = src[j + 128 * i];
#pragma unroll
        for (int i = 0; i < 16; i++) dst[j + 128 * i] = tmp[i];
    }

    // ---- packed weights for sums k0=2m (A) and k1=2m+1 (B) over 16 h elems
    const int k0 = 2 * m, k1 = 2 * m + 1;
    const float* r0 = (k0 < 4) ? (W_in + k0 * (HD + FD)) : (W_h + (k0 - 4) * HD);
    const float* r1 = (k1 < 4) ? (W_in + k1 * (HD + FD)) : (W_h + (k1 - 4) * HD);
    u64 wA[8], wB[8];
#pragma unroll
    for (int i = 0; i < 8; i++) {
        wA[i] = pack2(r0[sub * 16 + 2 * i], r0[sub * 16 + 2 * i + 1]);
        wB[i] = pack2(r1[sub * 16 + 2 * i], r1[sub * 16 + 2 * i + 1]);
    }

    float wo[4];
#pragma unroll
    for (int kk = 0; kk < 4; kk++) wo[kk] = W_out[j * 4 + kk];
    const float bo = b_out[j];

    // ---- cosine role for this lane (loop-invariant)
    //  m<2 (y sums): sub=0 -> cr_{2m}; 1 -> cz_{2m}; 2 -> cr_{2m+1}; 3 -> cz_{2m+1}
    //  m>=2 (q sums): sub=0 -> ch_{2(m-2)}; 2 -> ch_{2(m-2)+1}
    int slot = -1;
    float cadd = 0.0f;
    if (m < 2) {
        int kk = 2 * m + ((sub >> 1) & 1);
        if (sub < 4) {
            slot = ((sub & 1) == 0) ? kk : 4 + kk;     // cr_kk or cz_kk
            cadd = ((sub & 1) == 0) ? vqc_w[kk] : vqc_w[4 + kk];
        }
    } else {
        int kk = 2 * (m - 2) + ((sub >> 1) & 1);
        if (sub == 0 || sub == 2) {
            slot = 8 + kk;                              // ch_kk
            cadd = vqc_w[12 + kk] + b_h[kk];
        }
    }
    const bool use_p = (m < 2);
    const bool useB  = ((sub & 2) != 0);                // role uses sum k1
    const int  pidx  = 2 * m + ((sub >> 1) & 1);        // xs component (y lanes)

    float hj = 0.0f;
    h_sh[0][j] = 0.0f;

    // c_last = zeros
    out[(size_t)NB * T_STEPS * HD + (size_t)NB * HD + b * HD + j] = 0.0f;

    float* __restrict__ orow = out + (size_t)b * T_STEPS * HD + j;
    float* cbuf = cos_sh[wid];

    __syncthreads();

    float prev = 0.0f;

#pragma unroll 1
    for (int t = 0; t < T_STEPS; t++) {
        // h reads first: 4 LDS.128 per lane
        const ulonglong2* hp = reinterpret_cast<const ulonglong2*>(
            h_sh[t & 1] + sub * 16);
        ulonglong2 q0 = hp[0];
        ulonglong2 q1 = hp[1];
        ulonglong2 q2 = hp[2];
        ulonglong2 q3 = hp[3];

        // previous step's hidden-seq store, off the pre-barrier path
        if (t) orow[(size_t)(t - 1) * HD] = prev;

        // h-independent work hoisted off the critical path
        float4 P1 = *reinterpret_cast<const float4*>(xs + t * 8 + 4);
        float pc  = xs[t * 8 + (pidx & 3)];
        float o_x = fmaf(P1.x, wo[0],
                    fmaf(P1.y, wo[1], fmaf(P1.z, wo[2], fmaf(P1.w, wo[3], bo))));

        u64 aA0 = 0ull, aA1 = 0ull, aB0 = 0ull, aB1 = 0ull;
        aA0 = fma2(q0.x, wA[0], aA0); aA1 = fma2(q0.y, wA[1], aA1);
        aB0 = fma2(q0.x, wB[0], aB0); aB1 = fma2(q0.y, wB[1], aB1);
        aA0 = fma2(q1.x, wA[2], aA0); aA1 = fma2(q1.y, wA[3], aA1);
        aB0 = fma2(q1.x, wB[2], aB0); aB1 = fma2(q1.y, wB[3], aB1);
        aA0 = fma2(q2.x, wA[4], aA0); aA1 = fma2(q2.y, wA[5], aA1);
        aB0 = fma2(q2.x, wB[4], aB0); aB1 = fma2(q2.y, wB[5], aB1);
        aA0 = fma2(q3.x, wA[6], aA0); aA1 = fma2(q3.y, wA[7], aA1);
        aB0 = fma2(q3.x, wB[6], aB0); aB1 = fma2(q3.y, wB[7], aB1);

        aA0 = add2(aA0, aA1);
        aB0 = add2(aB0, aB1);
        float alo, ahi, blo, bhi;
        unpack2(aA0, alo, ahi);
        unpack2(aB0, blo, bhi);
        float sA = alo + ahi;
        float sB = blo + bhi;

        // 3-level butterfly within the 8-lane group
        sA += __shfl_xor_sync(0xffffffffu, sA, 1);
        sB += __shfl_xor_sync(0xffffffffu, sB, 1);
        sA += __shfl_xor_sync(0xffffffffu, sA, 2);
        sB += __shfl_xor_sync(0xffffffffu, sB, 2);
        sA += __shfl_xor_sync(0xffffffffu, sA, 4);
        sB += __shfl_xor_sync(0xffffffffu, sB, 4);

        // one warp-wide cosine computes this warp's 12 gate cosines
        float ssel = useB ? sB : sA;
        float arg  = ssel + cadd + (use_p ? pc : 0.0f);
        float cv   = __cosf(arg);
        if (slot >= 0) cbuf[slot] = cv;
        __syncwarp();

        float4 CR = *reinterpret_cast<const float4*>(cbuf + 0);
        float4 CZ = *reinterpret_cast<const float4*>(cbuf + 4);
        float4 CH = *reinterpret_cast<const float4*>(cbuf + 8);

        // z-expectations after CNOT ring: (C1C2C3, C0C1, C0C1C2, C0C1C2C3)
        float rm = CR.y * CR.z;
        float rA = CR.x * CR.y, rB = CR.x * rm;
        float o_r = fmaf(rm * CR.w, wo[0],
                    fmaf(rA, wo[1], fmaf(rB, wo[2], fmaf(rB * CR.w, wo[3], bo))));
        float Er = __expf(-o_r);                 // start r's MUFU chain early

        float hm = CH.y * CH.z;
        float hA = CH.x * CH.y, hB = CH.x * hm;
        float o_h = fmaf(hm * CH.w, wo[0],
                    fmaf(hA, wo[1], fmaf(hB, wo[2], fmaf(hB * CH.w, wo[3], bo))));

        float zm = CZ.y * CZ.z;
        float zA = CZ.x * CZ.y, zB = CZ.x * zm;
        float o_z = fmaf(zm * CZ.w, wo[0],
                    fmaf(zA, wo[1], fmaf(zB, wo[2], fmaf(zB * CZ.w, wo[3], bo))));

        float r = __fdividef(1.0f, 1.0f + Er);
        float z = fsig(o_z);
        float n = ftanhf(fmaf(r, o_h, o_x));

        hj = fmaf(z, hj - n, n);          // (1-z)*n + z*h

        h_sh[(t + 1) & 1][j] = hj;        // publish to other lanes

        __syncthreads();
        prev = hj;
    }

    orow[(size_t)(T_STEPS - 1) * HD] = prev;
    // h_last
    out[(size_t)NB * T_STEPS * HD + b * HD + j] = hj;
}

extern "C" void kernel_launch(void* const* d_in, const int* in_sizes, int n_in,
                              void* d_out, int out_size) {
    const float* x     = (const float*)d_in[0];
    const float* W_in  = (const float*)d_in[1];
    const float* b_in  = (const float*)d_in[2];
    const float* W_x   = (const float*)d_in[3];
    const float* b_x   = (const float*)d_in[4];
    const float* W_h   = (const float*)d_in[5];
    const float* b_h   = (const float*)d_in[6];
    const float* W_out = (const float*)d_in[7];
    const float* b_out = (const float*)d_in[8];
    const float* vqcw  = (const float*)d_in[9];
    float* out = (float*)d_out;

    qgru_prepass<<<592, 256>>>(x, W_in, b_in, W_x, b_x, vqcw);
    qgru_seq<<<NB, HD>>>(W_in, W_h, b_h, W_out, b_out, vqcw, out);
}